// round 15
// baseline (speedup 1.0000x reference)
#include <cuda_runtime.h>

// PaDiM Mahalanobis score map, GB300 sm_103a.
// Inputs (metadata order):
//   d_in[0] fmaps  f32 (8,448,56,56)
//   d_in[1] select int32 (100)
//   d_in[2] mean   f32 (100,56,56)
//   d_in[3] cov    f32 (100,100,56,56)  -- symmetric per pixel (A A^T)
//   d_in[4] min_score f32 scalar
//   d_in[5] max_score f32 scalar
// Output: f32 (8,224,224)

#define CT   448
#define C    100
#define HW   3136      // 56*56
#define NB   8
#define P    64        // pixels per block
#define NTHR 1024
#define NSL  24        // total d-slices (3 chunks x 8)
#define TOTS 2450      // total off-diagonal steps at 2-channel blocking
#define CHW  (C*HW)    // 313600

typedef unsigned long long u64;

// partial s^2 sums: [chunk][n][pixel]
__device__ float g_part[3 * NB * HW];
// sqrt'ed score map: [n][pixel]
__device__ float g_smap[NB * HW];

__device__ __forceinline__ u64 pk2(float lo, float hi) {
    u64 r; asm("mov.b64 %0, {%1, %2};" : "=l"(r) : "f"(lo), "f"(hi)); return r;
}
__device__ __forceinline__ float2 upk2(u64 a) {
    float2 f; asm("mov.b64 {%0, %1}, %2;" : "=f"(f.x), "=f"(f.y) : "l"(a)); return f;
}
__device__ __forceinline__ u64 add2(u64 a, u64 b) {
    u64 r; asm("add.rn.f32x2 %0, %1, %2;" : "=l"(r) : "l"(a), "l"(b)); return r;
}
__device__ __forceinline__ u64 mul2(u64 a, u64 b) {
    u64 r; asm("mul.rn.f32x2 %0, %1, %2;" : "=l"(r) : "l"(a), "l"(b)); return r;
}
__device__ __forceinline__ u64 fma2(u64 a, u64 b, u64 c) {
    u64 r; asm("fma.rn.f32x2 %0, %1, %2, %3;" : "=l"(r) : "l"(a), "l"(b), "l"(c)); return r;
}

// x tile: [c][p][n], n contiguous (32B per (c,p)).  100*64*8*4 = 204800 B
extern __shared__ float xs[];

__global__ void __launch_bounds__(NTHR, 1) padim_main(
    const float* __restrict__ fmaps,
    const int*   __restrict__ sel,
    const float* __restrict__ mean,
    const float* __restrict__ cov)
{
    __shared__ int sel_s[C];
    const int tid   = threadIdx.x;
    const int pbase = blockIdx.x * P;
    const int chunk = blockIdx.y;

    if (tid < C) sel_s[tid] = sel[tid];
    __syncthreads();

    // Build x tile (p fastest across lanes -> coalesced fmaps/mean loads)
    for (int i = tid; i < C * NB * P; i += NTHR) {
        int p = i & (P - 1);
        int n = (i >> 6) & 7;
        int c = i >> 9;
        float v = fmaps[(n * CT + sel_s[c]) * HW + pbase + p]
                - mean[c * HW + pbase + p];
        xs[(c * P + p) * 8 + n] = v;
    }
    __syncthreads();

    // thread mapping: lane = p_lo(16) + 16*nq  -> the 2 nq threads sharing a
    // cov value sit in the same warp; the coalescer merges their requests.
    const int lane = tid & 31;
    const int w    = tid >> 5;
    const int p    = (lane & 15) + 16 * (w & 3);  // pixel in tile (0..63)
    const int nq   = lane >> 4;                   // n quad: n in [4nq, 4nq+3]
    const int ds   = w >> 2;                      // 0..7
    const int slice = chunk * 8 + ds;             // 0..23
    const int pg   = pbase + p;
    const int xoff = 4 * nq;

    u64 acc0 = 0ull, acc1 = 0ull;   // packed accum: pair0 = (4nq,4nq+1), pair1

    // ---- off-diagonal sweep, 2-channel blocking ----
    // k-block k covers channels (2k, 2k+1), d in [2k+2, 99]: 98-2k steps.
    // base(k) = k*(99-k); total 2450 steps split into 24 slices.
    int g    = (slice * TOTS) / NSL;
    int gend = ((slice + 1) * TOTS) / NSL;
    int k = 0;
    while ((k + 1) * (98 - k) <= g) ++k;

    while (g < gend) {
        const int c0  = 2 * k;
        const int d0  = c0 + 2 + (g - k * (99 - k));
        const int nst = min(100 - d0, gend - g);

        float4 xa = *(const float4*)&xs[(c0 * P + p) * 8 + xoff];
        float4 xb = *(const float4*)&xs[((c0 + 1) * P + p) * 8 + xoff];
        u64 xc2_0p0 = pk2(xa.x + xa.x, xa.y + xa.y);
        u64 xc2_0p1 = pk2(xa.z + xa.z, xa.w + xa.w);
        u64 xc2_1p0 = pk2(xb.x + xb.x, xb.y + xb.y);
        u64 xc2_1p1 = pk2(xb.z + xb.z, xb.w + xb.w);

        u64 l00 = 0ull, l01 = 0ull, l10 = 0ull, l11 = 0ull;
        const float* cb = cov + (size_t)c0 * CHW + (size_t)d0 * HW + pg;

        #pragma unroll 4
        for (int s = 0; s < nst; ++s) {
            float v0 = cb[0];          // default policy: stays L2-resident
            float v1 = cb[CHW];        // across graph replays (75MB < 126MB L2)
            float4 xq = *(const float4*)&xs[((d0 + s) * P + p) * 8 + xoff];
            u64 xd0 = pk2(xq.x, xq.y);
            u64 xd1 = pk2(xq.z, xq.w);
            u64 dv0 = pk2(v0, v0);
            u64 dv1 = pk2(v1, v1);
            l00 = fma2(dv0, xd0, l00);
            l01 = fma2(dv0, xd1, l01);
            l10 = fma2(dv1, xd0, l10);
            l11 = fma2(dv1, xd1, l11);
            cb += HW;
        }

        acc0 = fma2(xc2_0p0, l00, acc0);
        acc0 = fma2(xc2_1p0, l10, acc0);
        acc1 = fma2(xc2_0p1, l01, acc1);
        acc1 = fma2(xc2_1p1, l11, acc1);

        g += nst;
        if (d0 + nst == 100) ++k;
    }

    // ---- diagonal 2x2 micro-blocks: block kk handled by slice kk%24 ----
    for (int kk = slice; kk < 50; kk += NSL) {
        const int c0 = 2 * kk;
        float4 xa = *(const float4*)&xs[(c0 * P + p) * 8 + xoff];
        float4 xb = *(const float4*)&xs[((c0 + 1) * P + p) * 8 + xoff];
        const float* cb = cov + (size_t)c0 * CHW + (size_t)c0 * HW + pg;
        float v00 = cb[0];              // (c0,   c0)
        float v01 = cb[HW];             // (c0,   c0+1)
        float v11 = cb[CHW + HW];       // (c0+1, c0+1)
        u64 x0p0 = pk2(xa.x, xa.y), x0p1 = pk2(xa.z, xa.w);
        u64 x1p0 = pk2(xb.x, xb.y), x1p1 = pk2(xb.z, xb.w);
        u64 d00 = pk2(v00, v00);
        u64 d01 = pk2(v01 + v01, v01 + v01);
        u64 d11 = pk2(v11, v11);
        acc0 = fma2(d00, mul2(x0p0, x0p0), acc0);
        acc0 = fma2(d01, mul2(x0p0, x1p0), acc0);
        acc0 = fma2(d11, mul2(x1p0, x1p0), acc0);
        acc1 = fma2(d00, mul2(x0p1, x0p1), acc1);
        acc1 = fma2(d01, mul2(x0p1, x1p1), acc1);
        acc1 = fma2(d11, mul2(x1p1, x1p1), acc1);
    }

    // ---- in-block reduction over the 8 d-slices ----
    __syncthreads();                 // all xs reads done
    u64* red = (u64*)xs;
    red[tid * 2]     = acc0;
    red[tid * 2 + 1] = acc1;
    __syncthreads();

    if (tid < 128) {
        u64 a = red[tid * 2], b = red[tid * 2 + 1];
        #pragma unroll
        for (int s2 = 1; s2 < 8; ++s2) {
            a = add2(a, red[(tid + 128 * s2) * 2]);
            b = add2(b, red[(tid + 128 * s2) * 2 + 1]);
        }
        float2 r0 = upk2(a), r1 = upk2(b);
        int pr  = (tid & 15) + 16 * ((tid >> 5) & 3);   // pixel
        int nqr = (tid >> 4) & 1;
        int base = (chunk * NB + 4 * nqr) * HW + pbase + pr;
        g_part[base]          = r0.x;
        g_part[base + HW]     = r0.y;
        g_part[base + 2 * HW] = r1.x;
        g_part[base + 3 * HW] = r1.y;
    }
}

// sum 3 partials -> sqrt
__global__ void padim_smap()
{
    int i = blockIdx.x * blockDim.x + threadIdx.x;
    if (i >= NB * HW) return;
    float s2 = g_part[i] + g_part[NB * HW + i] + g_part[2 * NB * HW + i];
    g_smap[i] = sqrtf(fmaxf(s2, 0.0f));
}

// half-pixel bilinear x4 + normalize; 4 output x per thread
__global__ void padim_finalize(float* __restrict__ out,
                               const float* __restrict__ minp,
                               const float* __restrict__ maxp)
{
    int idx = blockIdx.x * blockDim.x + threadIdx.x;  // over NB*224*56
    if (idx >= NB * 224 * 56) return;
    int q = idx % 56;
    int t = idx / 56;
    int y = t % 224;
    int n = t / 224;

    float sy = y * 0.25f - 0.375f;
    float fy = floorf(sy);
    float wy = sy - fy;
    int y0 = max((int)fy, 0);
    int y1 = min((int)fy + 1, 55);
    int cm = max(q - 1, 0);
    int cp = min(q + 1, 55);

    const float* s = g_smap + n * HW;
    float sm0 = s[y0 * 56 + cm], sm1 = s[y1 * 56 + cm];
    float s00 = s[y0 * 56 + q],  s01 = s[y1 * 56 + q];
    float sp0 = s[y0 * 56 + cp], sp1 = s[y1 * 56 + cp];

    float vm = sm0 + wy * (sm1 - sm0);
    float v0 = s00 + wy * (s01 - s00);
    float vp = sp0 + wy * (sp1 - sp0);

    float mn  = *minp;
    float inv = 1.0f / (*maxp - mn);

    float4 r;
    r.x = (vm + 0.625f * (v0 - vm) - mn) * inv;
    r.y = (vm + 0.875f * (v0 - vm) - mn) * inv;
    r.z = (v0 + 0.125f * (vp - v0) - mn) * inv;
    r.w = (v0 + 0.375f * (vp - v0) - mn) * inv;

    *(float4*)(out + (n * 224 + y) * 224 + 4 * q) = r;
}

extern "C" void kernel_launch(void* const* d_in, const int* in_sizes, int n_in,
                              void* d_out, int out_size)
{
    const float* fmaps = (const float*)d_in[0];
    const int*   sel   = (const int*)  d_in[1];
    const float* mean  = (const float*)d_in[2];
    const float* cov   = (const float*)d_in[3];
    const float* mn    = (const float*)d_in[4];
    const float* mx    = (const float*)d_in[5];
    float* out = (float*)d_out;

    const int smem = C * P * 8 * sizeof(float);  // 204800 B
    cudaFuncSetAttribute(padim_main, cudaFuncAttributeMaxDynamicSharedMemorySize, smem);

    dim3 grid(HW / P, 3);
    padim_main<<<grid, NTHR, smem>>>(fmaps, sel, mean, cov);

    padim_smap<<<(NB * HW + 255) / 256, 256>>>();

    int total = NB * 224 * 56;
    padim_finalize<<<(total + 255) / 256, 256>>>(out, mn, mx);
}

// round 17
// speedup vs baseline: 1.0092x; 1.0092x over previous
#include <cuda_runtime.h>

// PaDiM Mahalanobis score map, GB300 sm_103a.
// Inputs (metadata order):
//   d_in[0] fmaps  f32 (8,448,56,56)
//   d_in[1] select int32 (100)
//   d_in[2] mean   f32 (100,56,56)
//   d_in[3] cov    f32 (100,100,56,56)  -- symmetric per pixel (A A^T)
//   d_in[4] min_score f32 scalar
//   d_in[5] max_score f32 scalar
// Output: f32 (8,224,224)

#define CT   448
#define C    100
#define HW   3136      // 56*56
#define NB   8
#define P    64        // pixels per block
#define NTHR 1024
#define NSL  24        // total d-slices (3 chunks x 8)
#define TOTS 2450      // total off-diagonal steps at 2-channel blocking
#define CHW  (C*HW)    // 313600

typedef unsigned long long u64;

// partial s^2 sums: [chunk][n][pixel]
__device__ float g_part[3 * NB * HW];
// sqrt'ed score map: [n][pixel]
__device__ float g_smap[NB * HW];

__device__ __forceinline__ u64 pk2(float lo, float hi) {
    u64 r; asm("mov.b64 %0, {%1, %2};" : "=l"(r) : "f"(lo), "f"(hi)); return r;
}
__device__ __forceinline__ float2 upk2(u64 a) {
    float2 f; asm("mov.b64 {%0, %1}, %2;" : "=f"(f.x), "=f"(f.y) : "l"(a)); return f;
}
__device__ __forceinline__ u64 add2(u64 a, u64 b) {
    u64 r; asm("add.rn.f32x2 %0, %1, %2;" : "=l"(r) : "l"(a), "l"(b)); return r;
}
__device__ __forceinline__ u64 mul2(u64 a, u64 b) {
    u64 r; asm("mul.rn.f32x2 %0, %1, %2;" : "=l"(r) : "l"(a), "l"(b)); return r;
}
__device__ __forceinline__ u64 fma2(u64 a, u64 b, u64 c) {
    u64 r; asm("fma.rn.f32x2 %0, %1, %2, %3;" : "=l"(r) : "l"(a), "l"(b), "l"(c)); return r;
}

// x tile: [c][p][n], n contiguous (32B per (c,p)).  100*64*8*4 = 204800 B
extern __shared__ float xs[];

__global__ void __launch_bounds__(NTHR, 1) padim_main(
    const float* __restrict__ fmaps,
    const int*   __restrict__ sel,
    const float* __restrict__ mean,
    const float* __restrict__ cov)
{
    __shared__ int sel_s[C];
    const int tid   = threadIdx.x;
    const int pbase = blockIdx.x * P;
    const int chunk = blockIdx.y;

    if (tid < C) sel_s[tid] = sel[tid];
    __syncthreads();

    // Build x tile (p fastest across lanes -> coalesced fmaps/mean loads)
    for (int i = tid; i < C * NB * P; i += NTHR) {
        int p = i & (P - 1);
        int n = (i >> 6) & 7;
        int c = i >> 9;
        float v = fmaps[(n * CT + sel_s[c]) * HW + pbase + p]
                - mean[c * HW + pbase + p];
        xs[(c * P + p) * 8 + n] = v;
    }
    __syncthreads();

    // thread mapping: lane = p_lo(16) + 16*nq  -> the 2 nq threads sharing a
    // cov value sit in the same warp; the coalescer merges their requests.
    const int lane = tid & 31;
    const int w    = tid >> 5;
    const int p    = (lane & 15) + 16 * (w & 3);  // pixel in tile (0..63)
    const int nq   = lane >> 4;                   // n quad: n in [4nq, 4nq+3]
    const int ds   = w >> 2;                      // 0..7
    const int slice = chunk * 8 + ds;             // 0..23
    const int pg   = pbase + p;
    const int xoff = 4 * nq;

    u64 acc0 = 0ull, acc1 = 0ull;   // packed accum: pair0 = (4nq,4nq+1), pair1

    // ---- off-diagonal sweep, 2-channel blocking ----
    // k-block k covers channels (2k, 2k+1), d in [2k+2, 99]: 98-2k steps.
    // base(k) = k*(99-k); total 2450 steps split into 24 slices.
    int g    = (slice * TOTS) / NSL;
    int gend = ((slice + 1) * TOTS) / NSL;
    int k = 0;
    while ((k + 1) * (98 - k) <= g) ++k;

    while (g < gend) {
        const int c0  = 2 * k;
        const int d0  = c0 + 2 + (g - k * (99 - k));
        const int nst = min(100 - d0, gend - g);

        float4 xa = *(const float4*)&xs[(c0 * P + p) * 8 + xoff];
        float4 xb = *(const float4*)&xs[((c0 + 1) * P + p) * 8 + xoff];
        u64 xc2_0p0 = pk2(xa.x + xa.x, xa.y + xa.y);
        u64 xc2_0p1 = pk2(xa.z + xa.z, xa.w + xa.w);
        u64 xc2_1p0 = pk2(xb.x + xb.x, xb.y + xb.y);
        u64 xc2_1p1 = pk2(xb.z + xb.z, xb.w + xb.w);

        u64 l00 = 0ull, l01 = 0ull, l10 = 0ull, l11 = 0ull;
        const float* cb = cov + (size_t)c0 * CHW + (size_t)d0 * HW + pg;

        #pragma unroll 4
        for (int s = 0; s < nst; ++s) {
            float v0 = cb[0];          // default policy: stays L2-resident
            float v1 = cb[CHW];        // across graph replays (75MB < 126MB L2)
            float4 xq = *(const float4*)&xs[((d0 + s) * P + p) * 8 + xoff];
            u64 xd0 = pk2(xq.x, xq.y);
            u64 xd1 = pk2(xq.z, xq.w);
            u64 dv0 = pk2(v0, v0);
            u64 dv1 = pk2(v1, v1);
            l00 = fma2(dv0, xd0, l00);
            l01 = fma2(dv0, xd1, l01);
            l10 = fma2(dv1, xd0, l10);
            l11 = fma2(dv1, xd1, l11);
            cb += HW;
        }

        acc0 = fma2(xc2_0p0, l00, acc0);
        acc0 = fma2(xc2_1p0, l10, acc0);
        acc1 = fma2(xc2_0p1, l01, acc1);
        acc1 = fma2(xc2_1p1, l11, acc1);

        g += nst;
        if (d0 + nst == 100) ++k;
    }

    // ---- diagonal 2x2 micro-blocks: block kk handled by slice kk%24 ----
    for (int kk = slice; kk < 50; kk += NSL) {
        const int c0 = 2 * kk;
        float4 xa = *(const float4*)&xs[(c0 * P + p) * 8 + xoff];
        float4 xb = *(const float4*)&xs[((c0 + 1) * P + p) * 8 + xoff];
        const float* cb = cov + (size_t)c0 * CHW + (size_t)c0 * HW + pg;
        float v00 = cb[0];              // (c0,   c0)
        float v01 = cb[HW];             // (c0,   c0+1)
        float v11 = cb[CHW + HW];       // (c0+1, c0+1)
        u64 x0p0 = pk2(xa.x, xa.y), x0p1 = pk2(xa.z, xa.w);
        u64 x1p0 = pk2(xb.x, xb.y), x1p1 = pk2(xb.z, xb.w);
        u64 d00 = pk2(v00, v00);
        u64 d01 = pk2(v01 + v01, v01 + v01);
        u64 d11 = pk2(v11, v11);
        acc0 = fma2(d00, mul2(x0p0, x0p0), acc0);
        acc0 = fma2(d01, mul2(x0p0, x1p0), acc0);
        acc0 = fma2(d11, mul2(x1p0, x1p0), acc0);
        acc1 = fma2(d00, mul2(x0p1, x0p1), acc1);
        acc1 = fma2(d01, mul2(x0p1, x1p1), acc1);
        acc1 = fma2(d11, mul2(x1p1, x1p1), acc1);
    }

    // ---- in-block reduction over the 8 d-slices ----
    __syncthreads();                 // all xs reads done
    u64* red = (u64*)xs;
    red[tid * 2]     = acc0;
    red[tid * 2 + 1] = acc1;
    __syncthreads();

    if (tid < 128) {
        u64 a = red[tid * 2], b = red[tid * 2 + 1];
        #pragma unroll
        for (int s2 = 1; s2 < 8; ++s2) {
            a = add2(a, red[(tid + 128 * s2) * 2]);
            b = add2(b, red[(tid + 128 * s2) * 2 + 1]);
        }
        float2 r0 = upk2(a), r1 = upk2(b);
        int pr  = (tid & 15) + 16 * ((tid >> 5) & 3);   // pixel
        int nqr = (tid >> 4) & 1;
        int base = (chunk * NB + 4 * nqr) * HW + pbase + pr;
        g_part[base]          = r0.x;
        g_part[base + HW]     = r0.y;
        g_part[base + 2 * HW] = r1.x;
        g_part[base + 3 * HW] = r1.y;
    }
}

// sum 3 partials -> sqrt
__global__ void padim_smap()
{
    int i = blockIdx.x * blockDim.x + threadIdx.x;
    if (i >= NB * HW) return;
    float s2 = g_part[i] + g_part[NB * HW + i] + g_part[2 * NB * HW + i];
    g_smap[i] = sqrtf(fmaxf(s2, 0.0f));
}

// half-pixel bilinear x4 + normalize; 4 output x per thread
__global__ void padim_finalize(float* __restrict__ out,
                               const float* __restrict__ minp,
                               const float* __restrict__ maxp)
{
    int idx = blockIdx.x * blockDim.x + threadIdx.x;  // over NB*224*56
    if (idx >= NB * 224 * 56) return;
    int q = idx % 56;
    int t = idx / 56;
    int y = t % 224;
    int n = t / 224;

    float sy = y * 0.25f - 0.375f;
    float fy = floorf(sy);
    float wy = sy - fy;
    int y0 = max((int)fy, 0);
    int y1 = min((int)fy + 1, 55);
    int cm = max(q - 1, 0);
    int cp = min(q + 1, 55);

    const float* s = g_smap + n * HW;
    float sm0 = s[y0 * 56 + cm], sm1 = s[y1 * 56 + cm];
    float s00 = s[y0 * 56 + q],  s01 = s[y1 * 56 + q];
    float sp0 = s[y0 * 56 + cp], sp1 = s[y1 * 56 + cp];

    float vm = sm0 + wy * (sm1 - sm0);
    float v0 = s00 + wy * (s01 - s00);
    float vp = sp0 + wy * (sp1 - sp0);

    float mn  = *minp;
    float inv = 1.0f / (*maxp - mn);

    float4 r;
    r.x = (vm + 0.625f * (v0 - vm) - mn) * inv;
    r.y = (vm + 0.875f * (v0 - vm) - mn) * inv;
    r.z = (v0 + 0.125f * (vp - v0) - mn) * inv;
    r.w = (v0 + 0.375f * (vp - v0) - mn) * inv;

    *(float4*)(out + (n * 224 + y) * 224 + 4 * q) = r;
}

extern "C" void kernel_launch(void* const* d_in, const int* in_sizes, int n_in,
                              void* d_out, int out_size)
{
    const float* fmaps = (const float*)d_in[0];
    const int*   sel   = (const int*)  d_in[1];
    const float* mean  = (const float*)d_in[2];
    const float* cov   = (const float*)d_in[3];
    const float* mn    = (const float*)d_in[4];
    const float* mx    = (const float*)d_in[5];
    float* out = (float*)d_out;

    const int smem = C * P * 8 * sizeof(float);  // 204800 B
    cudaFuncSetAttribute(padim_main, cudaFuncAttributeMaxDynamicSharedMemorySize, smem);

    dim3 grid(HW / P, 3);
    padim_main<<<grid, NTHR, smem>>>(fmaps, sel, mean, cov);

    padim_smap<<<(NB * HW + 255) / 256, 256>>>();

    int total = NB * 224 * 56;
    padim_finalize<<<(total + 255) / 256, 256>>>(out, mn, mx);
}